// round 15
// baseline (speedup 1.0000x reference)
#include <cuda_runtime.h>
#include <cuda_bf16.h>
#include <cuda_fp16.h>
#include <cstdint>
#include <math.h>

// Problem constants
#define BATCH   4
#define S_LEN   2048
#define DMODEL  256
#define NHEADS  8
#define HD      32
#define M_ROWS  (BATCH * S_LEN)   // 8192
#define MWORDS  (S_LEN / 32)      // 64 mask words per row
#define NBH     (BATCH * NHEADS)  // 32

// Scratch (device globals: allocation-free per harness rules)
__device__ float          g_V[M_ROWS * DMODEL];
__device__ unsigned       g_MB[BATCH * S_LEN * MWORDS];        // packed mask bits
__device__ __half         g_Qp16[(size_t)NBH * S_LEN * 32];    // attn Q fp16 (SC folded), swizzled 64B rows
__device__ __half         g_Kp16[(size_t)NBH * S_LEN * 32];    // attn K fp16, swizzled 64B rows
__device__ __half         g_Vp16[(size_t)NBH * 32 * 2048];     // attn V^T fp16, 4KB/tile swizzled
// GEMM operand packs: A-format [blk 0..7][row][64 bf16], SW128 swizzled per row
__device__ __nv_bfloat16  g_Aq[(size_t)8 * M_ROWS * 64];
__device__ __nv_bfloat16  g_Ak[(size_t)8 * M_ROWS * 64];
__device__ __nv_bfloat16  g_Av[(size_t)8 * M_ROWS * 64];
__device__ __nv_bfloat16  g_Op[(size_t)8 * M_ROWS * 64];       // attn output, packed directly
__device__ __nv_bfloat16  g_Wp[(size_t)4 * 8 * 256 * 64];      // weights q,k,v,o

#define ATTN_SC (0.17677669529663687f * 1.4426950408889634f)   // 1/sqrt(32)*log2e

// ---------------------------------------------------------------------------
// Helpers
// ---------------------------------------------------------------------------
__device__ __forceinline__ uint32_t smem_u32(const void* p) {
    uint32_t a;
    asm("{ .reg .u64 t; cvta.to.shared.u64 t, %1; cvt.u32.u64 %0, t; }" : "=r"(a) : "l"(p));
    return a;
}
__device__ __forceinline__ float ex2(float x) {
    float y; asm("ex2.approx.f32 %0, %1;" : "=f"(y) : "f"(x)); return y;
}
// pack two fp32 -> bf16x2 (lo = p0, hi = p1)
#define CVT_BF16X2(result, p0, p1) \
    asm("cvt.rn.satfinite.bf16x2.f32 %0, %1, %2;" : "=r"(result) : "f"(p1), "f"(p0))
// pack two fp32 -> f16x2 (lo = p0, hi = p1)
#define CVT_F16X2(result, p0, p1) \
    asm("cvt.rn.f16x2.f32 %0, %1, %2;" : "=r"(result) : "f"(p1), "f"(p0))

__device__ __forceinline__ void ldm_x4(uint32_t (&r)[4], uint32_t addr) {
    asm volatile("ldmatrix.sync.aligned.m8n8.x4.shared.b16 {%0,%1,%2,%3}, [%4];"
                 : "=r"(r[0]), "=r"(r[1]), "=r"(r[2]), "=r"(r[3]) : "r"(addr));
}
__device__ __forceinline__ void mma_bf16(float (&d)[4], const uint32_t* a, const uint32_t* b) {
    asm volatile("mma.sync.aligned.m16n8k16.row.col.f32.bf16.bf16.f32 "
                 "{%0,%1,%2,%3}, {%4,%5,%6,%7}, {%8,%9}, {%0,%1,%2,%3};"
                 : "+f"(d[0]), "+f"(d[1]), "+f"(d[2]), "+f"(d[3])
                 : "r"(a[0]), "r"(a[1]), "r"(a[2]), "r"(a[3]), "r"(b[0]), "r"(b[1]));
}
__device__ __forceinline__ void mma_f16(float (&d)[4], const uint32_t* a, const uint32_t* b) {
    asm volatile("mma.sync.aligned.m16n8k16.row.col.f32.f16.f16.f32 "
                 "{%0,%1,%2,%3}, {%4,%5,%6,%7}, {%8,%9}, {%0,%1,%2,%3};"
                 : "+f"(d[0]), "+f"(d[1]), "+f"(d[2]), "+f"(d[3])
                 : "r"(a[0]), "r"(a[1]), "r"(a[2]), "r"(a[3]), "r"(b[0]), "r"(b[1]));
}

#define CP16(dst, src) \
    asm volatile("cp.async.cg.shared.global [%0], [%1], 16;" :: "r"(dst), "l"(src))
#define CP_COMMIT() asm volatile("cp.async.commit_group;" ::: "memory")
#define CP_WAIT0()  asm volatile("cp.async.wait_group 0;" ::: "memory")
#define CPG_WAIT1() asm volatile("cp.async.wait_group 1;" ::: "memory")

// ---------------------------------------------------------------------------
// Mask bit-pack v2: one thread = 8 elements (two int4 loads -> one byte).
// ---------------------------------------------------------------------------
__global__ __launch_bounds__(256) void pack_mask_kernel(
    const int4* __restrict__ mask, unsigned char* __restrict__ bits)
{
    int idx = blockIdx.x * 256 + threadIdx.x;
    int4 a = mask[idx * 2];
    int4 b = mask[idx * 2 + 1];
    unsigned byte = (unsigned)(a.x != 0)
                  | ((unsigned)(a.y != 0) << 1)
                  | ((unsigned)(a.z != 0) << 2)
                  | ((unsigned)(a.w != 0) << 3)
                  | ((unsigned)(b.x != 0) << 4)
                  | ((unsigned)(b.y != 0) << 5)
                  | ((unsigned)(b.z != 0) << 6)
                  | ((unsigned)(b.w != 0) << 7);
    bits[idx] = (unsigned char)byte;
}

// ---------------------------------------------------------------------------
// pack_a3 v2 (vectorized): one thread = 4 dims -> hi quad + lo quad (uint2 x2)
// ---------------------------------------------------------------------------
__global__ __launch_bounds__(256) void pack_a3_kernel(
    const float* __restrict__ q, const float* __restrict__ k, const float* __restrict__ v,
    __nv_bfloat16* __restrict__ Aq, __nv_bfloat16* __restrict__ Ak, __nv_bfloat16* __restrict__ Av)
{
    const float* src; __nv_bfloat16* dst;
    if (blockIdx.y == 0)      { src = q; dst = Aq; }
    else if (blockIdx.y == 1) { src = k; dst = Ak; }
    else                      { src = v; dst = Av; }
    int idx = blockIdx.x * 256 + threadIdx.x;     // 8 blk * 8192 m * 8 c4
    int c4  = idx & 7;
    int m   = (idx >> 3) & (M_ROWS - 1);
    int blk = (idx >> 16) & 7;
    float4 v4 = *(const float4*)&src[(size_t)m * DMODEL + blk * 32 + c4 * 4];
    uint32_t h0, h1, l0, l1;
    CVT_BF16X2(h0, v4.x, v4.y);
    CVT_BF16X2(h1, v4.z, v4.w);
    float hx = __uint_as_float(h0 << 16), hy = __uint_as_float(h0 & 0xffff0000u);
    float hz = __uint_as_float(h1 << 16), hw = __uint_as_float(h1 & 0xffff0000u);
    CVT_BF16X2(l0, v4.x - hx, v4.y - hy);
    CVT_BF16X2(l1, v4.z - hz, v4.w - hw);
    uint32_t* dp = (uint32_t*)(dst + (((size_t)blk * M_ROWS + m) << 6));
    const int sw = (m & 7) << 3;
    const int chi = (c4 * 4) ^ sw;          // bf16 index of hi quad
    const int clo = (32 + c4 * 4) ^ sw;     // bf16 index of lo quad
    *(uint2*)&dp[chi >> 1] = make_uint2(h0, h1);
    *(uint2*)&dp[clo >> 1] = make_uint2(l0, l1);
}

// ---------------------------------------------------------------------------
// Pack all 4 weight matrices: [w][blk][n][64], swizzled
// ---------------------------------------------------------------------------
__global__ __launch_bounds__(256) void pack_w_kernel(
    const float* __restrict__ Wq, const float* __restrict__ Wk,
    const float* __restrict__ Wv, const float* __restrict__ Wo,
    __nv_bfloat16* __restrict__ Wp)
{
    int idx = blockIdx.x * 256 + threadIdx.x;     // 4 * 8 * 256 * 64
    int c   = idx & 63;
    int n   = (idx >> 6) & 255;
    int blk = (idx >> 14) & 7;
    int w   = idx >> 17;
    const float* W = (w == 0) ? Wq : (w == 1) ? Wk : (w == 2) ? Wv : Wo;
    int d = blk * 32 + (c & 31);
    float val = W[(size_t)n * DMODEL + d];
    __nv_bfloat16 hi = __float2bfloat16(val);
    __nv_bfloat16 out = (c < 32) ? hi : __float2bfloat16(val - __bfloat162float(hi));
    Wp[(((size_t)(w * 8 + blk) * 256 + n) << 6) + (c ^ ((n & 7) << 3))] = out;
}

// ---------------------------------------------------------------------------
// V pack (fp16 single image): per (b,h,ktile): V^T 32d x 64key, 128B rows
// ---------------------------------------------------------------------------
__global__ __launch_bounds__(256) void pack_v16_kernel(
    const float* __restrict__ V, __half* __restrict__ Vp)
{
    int idx = blockIdx.x * 256 + threadIdx.x;      // NBH*32*32*64
    int key = idx & 63;
    int d   = (idx >> 6) & 31;
    int t   = (idx >> 11) & 31;
    int bh  = idx >> 16;
    int b = bh >> 3, h = bh & 7;
    float v = V[(size_t)(b * S_LEN + t * 64 + key) * DMODEL + h * HD + d];
    Vp[(size_t)bh * 65536 + t * 2048 + d * 64 + (key ^ ((d & 7) << 3))] = __float2half_rn(v);
}

// ---------------------------------------------------------------------------
// Tensor-core GEMM: C[M,256] = A[M,256] @ W^T + bias, bf16 hi/lo 3-term.
// MODE 0: fp32 output. MODE 1: fp16 attn-image output ((val+bias)*oscale).
// ---------------------------------------------------------------------------
#define GEMM_SMEM 98304

template <int MODE>
__device__ __forceinline__ void gemm_tc_body(
    const __nv_bfloat16* __restrict__ Ap, const __nv_bfloat16* __restrict__ Wp,
    const float* __restrict__ bias, void* __restrict__ Cout, float oscale, char* smem)
{
    const uint32_t sb = smem_u32(smem);
    const int tid = threadIdx.x, lane = tid & 31, wid = tid >> 5;
    const int n0 = blockIdx.x * 64, m0 = blockIdx.y * 128;
    const char* Ab = (const char*)Ap;
    const char* Wb = (const char*)Wp;

    auto stage = [&](int t, uint32_t buf) {
        #pragma unroll
        for (int i = 0; i < 8; i++) {
            int g = i * 256 + tid;
            int blk = g >> 10, row = (g >> 3) & 127, ch = g & 7;
            CP16(sb + buf + blk * 16384 + row * 128 + ch * 16,
                 Ab + ((size_t)(t * 2 + blk) * M_ROWS + m0 + row) * 128 + ch * 16);
        }
        #pragma unroll
        for (int i = 0; i < 4; i++) {
            int g = i * 256 + tid;
            int blk = g >> 9, row = (g >> 3) & 63, ch = g & 7;
            CP16(sb + buf + 32768 + blk * 8192 + row * 128 + ch * 16,
                 Wb + ((size_t)(t * 2 + blk) * 256 + n0 + row) * 128 + ch * 16);
        }
        CP_COMMIT();
    };

    stage(0, 0);

    float c[8][4];
    #pragma unroll
    for (int i = 0; i < 8; i++)
        #pragma unroll
        for (int j = 0; j < 4; j++) c[i][j] = 0.f;

    const int m_off = (lane & 7) + ((lane >> 3) & 1) * 8;
    const int coff  = (lane >> 4) & 1;
    const int m = wid * 16 + m_off;
    const int kb_row = (lane & 7) + ((lane >> 4) & 1) * 8;
    const int kb_c   = (lane >> 3) & 1;

    for (int t = 0; t < 4; t++) {
        if (t < 3) { stage(t + 1, ((t + 1) & 1) * 49152); CPG_WAIT1(); }
        else       { CP_WAIT0(); }
        __syncthreads();

        const uint32_t abase = sb + (t & 1) * 49152;
        const uint32_t wbase = abase + 32768;

        #pragma unroll
        for (int k16 = 0; k16 < 4; k16++) {
            const int ablk = k16 >> 1;
            const int ch = 2 * (k16 & 1) + coff;
            const uint32_t arow = abase + ablk * 16384 + m * 128;
            uint32_t afh[4], afl[4];
            ldm_x4(afh, arow + (((ch)     ^ (m & 7)) << 4));
            ldm_x4(afl, arow + (((ch + 4) ^ (m & 7)) << 4));
            #pragma unroll
            for (int np = 0; np < 4; np++) {
                const int n = np * 16 + kb_row;
                const uint32_t wrow = wbase + ablk * 8192 + n * 128;
                const int wch = 2 * (k16 & 1) + kb_c;
                uint32_t bhf[4], blf[4];
                ldm_x4(bhf, wrow + (((wch)     ^ (n & 7)) << 4));
                mma_bf16(c[2 * np],     afh, bhf + 0);
                mma_bf16(c[2 * np + 1], afh, bhf + 2);
                mma_bf16(c[2 * np],     afl, bhf + 0);
                mma_bf16(c[2 * np + 1], afl, bhf + 2);
                ldm_x4(blf, wrow + (((wch + 4) ^ (n & 7)) << 4));
                mma_bf16(c[2 * np],     afh, blf + 0);
                mma_bf16(c[2 * np + 1], afh, blf + 2);
            }
        }
        __syncthreads();
    }

    const int r0 = m0 + wid * 16 + (lane >> 2);
    if (MODE == 0) {
        float* C = (float*)Cout;
        #pragma unroll
        for (int np = 0; np < 4; np++) {
            #pragma unroll
            for (int half = 0; half < 2; half++) {
                const int col = n0 + np * 16 + half * 8 + (lane & 3) * 2;
                const float b0 = bias[col], b1 = bias[col + 1];
                float* p0 = C + (size_t)r0 * DMODEL + col;
                *(float2*)p0 = make_float2(c[2 * np + half][0] + b0, c[2 * np + half][1] + b1);
                *(float2*)(p0 + 8 * DMODEL) = make_float2(c[2 * np + half][2] + b0, c[2 * np + half][3] + b1);
            }
        }
    } else {
        // fp16 attn image: row (b,h,s) -> 32 halves at ((b*8+h)*2048+s)*32,
        // halves index d ^ (((s>>1)&3)<<3). Note sw(s) == sw(s+8).
        uint32_t* P32 = (uint32_t*)Cout;
        const int bb = r0 >> 11, s = r0 & (S_LEN - 1);
        const int sw = ((s >> 1) & 3) << 3;
        #pragma unroll
        for (int np = 0; np < 4; np++) {
            #pragma unroll
            for (int half = 0; half < 2; half++) {
                const int col = n0 + np * 16 + half * 8 + (lane & 3) * 2;
                const int hh = col >> 5, d = col & 31;
                const float b0 = bias[col], b1 = bias[col + 1];
                const size_t base = ((size_t)(bb * 8 + hh) * S_LEN + s) * 32;
                uint32_t p01, p23;
                CVT_F16X2(p01, (c[2 * np + half][0] + b0) * oscale,
                               (c[2 * np + half][1] + b1) * oscale);
                CVT_F16X2(p23, (c[2 * np + half][2] + b0) * oscale,
                               (c[2 * np + half][3] + b1) * oscale);
                P32[(base + (d ^ sw)) >> 1]       = p01;   // row s
                P32[(base + 256 + (d ^ sw)) >> 1] = p23;   // row s+8
            }
        }
    }
}

__global__ __launch_bounds__(256, 2) void gemm_tc_qkv(
    const __nv_bfloat16* __restrict__ Aq, const __nv_bfloat16* __restrict__ Ak,
    const __nv_bfloat16* __restrict__ Av, const __nv_bfloat16* __restrict__ Wp,
    const float* __restrict__ bq, const float* __restrict__ bk, const float* __restrict__ bv,
    __half* __restrict__ Qp, __half* __restrict__ Kp, float* __restrict__ Vo)
{
    extern __shared__ char smem[];
    if (blockIdx.z == 0)
        gemm_tc_body<1>(Aq, Wp,                      bq, Qp, ATTN_SC, smem);
    else if (blockIdx.z == 1)
        gemm_tc_body<1>(Ak, Wp + (size_t)1 * 131072, bk, Kp, 1.0f,    smem);
    else
        gemm_tc_body<0>(Av, Wp + (size_t)2 * 131072, bv, Vo, 1.0f,    smem);
}

__global__ __launch_bounds__(256, 2) void gemm_tc_one(
    const __nv_bfloat16* __restrict__ Ap, const __nv_bfloat16* __restrict__ Wp,
    const float* __restrict__ bias, float* __restrict__ C)
{
    extern __shared__ char smem[];
    gemm_tc_body<0>(Ap, Wp, bias, C, 1.0f, smem);
}

// ---------------------------------------------------------------------------
// fp16 single-pass mma flash attention, 128-key iterations (2 x 64 subtiles).
// Softmax fused into PV per k16 (ap shrinks 16->4 regs); 3 CTAs/SM target.
// smem: KV double buffer [2][16KB] at 0 (K 8KB | V 8KB); Q fp16 8KB at 32KB.
// ---------------------------------------------------------------------------
#define SM_KV 0
#define SM_Q  32768
#define ATTN_SMEM 40960

__global__ __launch_bounds__(256, 3) void attn_mma_kernel(
    const __half* __restrict__ Qp, const __half* __restrict__ Kp,
    const __half* __restrict__ Vp, const unsigned* __restrict__ mbits)
{
    extern __shared__ char smem[];
    const uint32_t sb = smem_u32(smem);
    const int tid = threadIdx.x;
    const int lane = tid & 31, wid = tid >> 5;
    const int b = blockIdx.z, h = blockIdx.y;
    const int q0 = blockIdx.x * 128;
    const int bh = b * NHEADS + h;

    const char* ksrc = (const char*)(Kp + (size_t)bh * 65536);
    const char* vsrc = (const char*)(Vp + (size_t)bh * 65536);
    const char* qsrc = (const char*)(Qp + ((size_t)bh * S_LEN + q0) * 32);

    // ---- prefetch Q tile (8KB) + KV iteration 0 (16KB) ----
    {
        uint32_t dq = sb + SM_Q;
        CP16(dq + tid * 16,         qsrc + tid * 16);
        CP16(dq + (tid + 256) * 16, qsrc + (tid + 256) * 16);
        uint32_t d0 = sb + SM_KV;
        CP16(d0 + tid * 16,                ksrc + tid * 16);
        CP16(d0 + (tid + 256) * 16,        ksrc + (tid + 256) * 16);
        CP16(d0 + 8192 + tid * 16,         vsrc + tid * 16);
        CP16(d0 + 8192 + (tid + 256) * 16, vsrc + (tid + 256) * 16);
        CP_COMMIT();
    }
    CP_WAIT0();
    __syncthreads();

    // ---- Q A-fragments (fp16, single image) ----
    uint32_t qf[2][4];
    {
        const int m_off = (lane & 7) + ((lane >> 3) & 1) * 8;
        const int coff  = (lane >> 4) & 1;
        const int m = wid * 16 + m_off;
        const uint32_t qrow = sb + SM_Q + m * 64;
        const int swq = (m >> 1) & 3;
        #pragma unroll
        for (int k16 = 0; k16 < 2; k16++) {
            int ch = 2 * k16 + coff;
            ldm_x4(qf[k16], qrow + ((ch ^ swq) << 4));
        }
    }

    const int kb_row = (lane & 7) + ((lane >> 4) & 1) * 8;
    const int kb_c   = (lane >> 3) & 1;

    const unsigned* mb0 = mbits + (size_t)(b * S_LEN + q0 + wid * 16 + (lane >> 2)) * MWORDS;
    const unsigned* mb1 = mb0 + 8 * MWORDS;

    float l0 = 0.f, l1 = 0.f;
    float o[4][4];
    #pragma unroll
    for (int i = 0; i < 4; i++)
        #pragma unroll
        for (int j = 0; j < 4; j++) o[i][j] = 0.f;

    for (int it = 0; it < 16; it++) {
        if (it) { CP_WAIT0(); __syncthreads(); }

        // prefetch it+1 into the other slot (safe: slot last read at it-1)
        if (it < 15) {
            uint32_t d1 = sb + SM_KV + ((it + 1) & 1) * 16384;
            const char* ks = ksrc + (size_t)(it + 1) * 8192;
            const char* vs = vsrc + (size_t)(it + 1) * 8192;
            CP16(d1 + tid * 16,                ks + tid * 16);
            CP16(d1 + (tid + 256) * 16,        ks + (tid + 256) * 16);
            CP16(d1 + 8192 + tid * 16,         vs + tid * 16);
            CP16(d1 + 8192 + (tid + 256) * 16, vs + (tid + 256) * 16);
            CP_COMMIT();
        }

        const uint32_t slot = sb + SM_KV + (it & 1) * 16384;

        #pragma unroll
        for (int sub = 0; sub < 2; sub++) {
            const uint32_t kbase = slot + sub * 4096;
            const uint32_t vbase = slot + 8192 + sub * 4096;

            // ---- QK^T (fp16): 8 ldm + 16 mma ----
            float c[8][4];
            #pragma unroll
            for (int i = 0; i < 8; i++)
                #pragma unroll
                for (int j = 0; j < 4; j++) c[i][j] = 0.f;

            #pragma unroll
            for (int k16 = 0; k16 < 2; k16++) {
                #pragma unroll
                for (int np = 0; np < 4; np++) {
                    const int key = np * 16 + kb_row;
                    const int ch  = 2 * k16 + kb_c;
                    uint32_t bf[4];
                    ldm_x4(bf, kbase + key * 64 + ((ch ^ ((key >> 1) & 3)) << 4));
                    mma_f16(c[2 * np],     qf[k16], bf + 0);
                    mma_f16(c[2 * np + 1], qf[k16], bf + 2);
                }
            }

            // ---- fused softmax + PV per k16 (ap lives 4 regs only) ----
            const uint64_t mw0 = *(const uint64_t*)(mb0 + it * 4 + sub * 2);
            const uint64_t mw1 = *(const uint64_t*)(mb1 + it * 4 + sub * 2);
            #pragma unroll
            for (int k16 = 0; k16 < 4; k16++) {
                uint32_t ap[4];
                #pragma unroll
                for (int half = 0; half < 2; half++) {
                    const int j = 2 * k16 + half;
                    const int colb = j * 8 + (lane & 3) * 2;
                    float p0 = ((mw0 >> colb)       & 1) ? ex2(c[j][0]) : 0.f;
                    float p1 = ((mw0 >> (colb + 1)) & 1) ? ex2(c[j][1]) : 0.f;
                    float p2 = ((mw1 >> colb)       & 1) ? ex2(c[j][2]) : 0.f;
                    float p3 = ((mw1 >> (colb + 1)) & 1) ? ex2(c[j][3]) : 0.f;
                    l0 += p0 + p1; l1 += p2 + p3;
                    CVT_F16X2(ap[half * 2],     p0, p1);
                    CVT_F16X2(ap[half * 2 + 1], p2, p3);
                }
                #pragma unroll
                for (int np = 0; np < 2; np++) {
                    const int d  = np * 16 + kb_row;
                    const int ch = 2 * k16 + kb_c;
                    uint32_t bv[4];
                    ldm_x4(bv, vbase + d * 128 + ((ch ^ (d & 7)) << 4));
                    mma_f16(o[2 * np],     ap, bv + 0);
                    mma_f16(o[2 * np + 1], ap, bv + 2);
                }
            }
        }
    }

    // ---- finalize: normalize and write packed bf16 hi/lo GEMM-A format ----
    l0 += __shfl_xor_sync(0xffffffffu, l0, 1);
    l0 += __shfl_xor_sync(0xffffffffu, l0, 2);
    l1 += __shfl_xor_sync(0xffffffffu, l1, 1);
    l1 += __shfl_xor_sync(0xffffffffu, l1, 2);
    const float inv0 = 1.f / l0, inv1 = 1.f / l1;

    const int r0g = q0 + wid * 16 + (lane >> 2);
    const int r1g = r0g + 8;
    uint32_t* Op32 = (uint32_t*)g_Op;
    const size_t base0 = ((size_t)h * M_ROWS + b * S_LEN + r0g) * 32;
    const size_t base1 = ((size_t)h * M_ROWS + b * S_LEN + r1g) * 32;
    const int sw0 = (r0g & 7) << 3;
    const int sw1 = (r1g & 7) << 3;
    #pragma unroll
    for (int j = 0; j < 4; j++) {
        const int d = j * 8 + (lane & 3) * 2;
        float v0 = o[j][0] * inv0, v1 = o[j][1] * inv0;
        float v2 = o[j][2] * inv1, v3 = o[j][3] * inv1;
        uint32_t h01, h23;
        CVT_BF16X2(h01, v0, v1);
        CVT_BF16X2(h23, v2, v3);
        float r0l = v0 - __uint_as_float(h01 << 16);
        float r1l = v1 - __uint_as_float(h01 & 0xffff0000u);
        float r2l = v2 - __uint_as_float(h23 << 16);
        float r3l = v3 - __uint_as_float(h23 & 0xffff0000u);
        uint32_t l01, l23;
        CVT_BF16X2(l01, r0l, r1l);
        CVT_BF16X2(l23, r2l, r3l);
        Op32[base0 + (((d)      ^ sw0) >> 1)] = h01;
        Op32[base0 + (((32 + d) ^ sw0) >> 1)] = l01;
        Op32[base1 + (((d)      ^ sw1) >> 1)] = h23;
        Op32[base1 + (((32 + d) ^ sw1) >> 1)] = l23;
    }
}

// ---------------------------------------------------------------------------
// Launch
// ---------------------------------------------------------------------------
extern "C" void kernel_launch(void* const* d_in, const int* in_sizes, int n_in,
                              void* d_out, int out_size)
{
    const float* query = (const float*)d_in[0];
    const float* key   = (const float*)d_in[1];
    const float* value = (const float*)d_in[2];
    const int*   mask  = (const int*)  d_in[3];
    const float* Wq = (const float*)d_in[4];
    const float* bq = (const float*)d_in[5];
    const float* Wk = (const float*)d_in[6];
    const float* bk = (const float*)d_in[7];
    const float* Wv = (const float*)d_in[8];
    const float* bv = (const float*)d_in[9];
    const float* Wo = (const float*)d_in[10];
    const float* bo = (const float*)d_in[11];
    float* out = (float*)d_out;

    float* Vb;
    unsigned* MBp;
    __half *Qpp, *Kpp, *Vpp;
    __nv_bfloat16 *Aq, *Ak, *Av, *Op, *Wp;
    cudaGetSymbolAddress((void**)&Vb, g_V);
    cudaGetSymbolAddress((void**)&MBp, g_MB);
    cudaGetSymbolAddress((void**)&Qpp, g_Qp16);
    cudaGetSymbolAddress((void**)&Kpp, g_Kp16);
    cudaGetSymbolAddress((void**)&Vpp, g_Vp16);
    cudaGetSymbolAddress((void**)&Aq, g_Aq);
    cudaGetSymbolAddress((void**)&Ak, g_Ak);
    cudaGetSymbolAddress((void**)&Av, g_Av);
    cudaGetSymbolAddress((void**)&Op, g_Op);
    cudaGetSymbolAddress((void**)&Wp, g_Wp);

    cudaFuncSetAttribute(attn_mma_kernel, cudaFuncAttributeMaxDynamicSharedMemorySize, ATTN_SMEM);
    cudaFuncSetAttribute(gemm_tc_qkv, cudaFuncAttributeMaxDynamicSharedMemorySize, GEMM_SMEM);
    cudaFuncSetAttribute(gemm_tc_one, cudaFuncAttributeMaxDynamicSharedMemorySize, GEMM_SMEM);

    pack_mask_kernel<<<(BATCH * S_LEN * S_LEN) / 8 / 256, 256>>>(
        (const int4*)mask, (unsigned char*)MBp);
    pack_w_kernel<<<(4 * 8 * 256 * 64) / 256, 256>>>(Wq, Wk, Wv, Wo, Wp);
    pack_a3_kernel<<<dim3((8 * M_ROWS * 8) / 256, 3), 256>>>(query, key, value, Aq, Ak, Av);

    gemm_tc_qkv<<<dim3(4, 64, 3), 256, GEMM_SMEM>>>(Aq, Ak, Av, Wp,
                                                    bq, bk, bv, Qpp, Kpp, Vb);

    pack_v16_kernel<<<(NBH * 32 * 32 * 64) / 256, 256>>>(Vb, Vpp);

    dim3 attn_grid(S_LEN / 128, NHEADS, BATCH);   // (16, 8, 4)
    attn_mma_kernel<<<attn_grid, 256, ATTN_SMEM>>>(Qpp, Kpp, Vpp, MBp);

    gemm_tc_one<<<dim3(4, 64), 256, GEMM_SMEM>>>(Op, Wp + (size_t)3 * 131072, bo, out);
}

// round 16
// speedup vs baseline: 1.1596x; 1.1596x over previous
#include <cuda_runtime.h>
#include <cuda_bf16.h>
#include <cuda_fp16.h>
#include <cstdint>
#include <math.h>

// Problem constants
#define BATCH   4
#define S_LEN   2048
#define DMODEL  256
#define NHEADS  8
#define HD      32
#define M_ROWS  (BATCH * S_LEN)   // 8192
#define MWORDS  (S_LEN / 32)      // 64 mask words per row
#define NBH     (BATCH * NHEADS)  // 32

// Scratch (device globals: allocation-free per harness rules)
__device__ float          g_V[M_ROWS * DMODEL];
__device__ unsigned       g_MB[BATCH * S_LEN * MWORDS];        // packed mask bits
__device__ __half         g_Qp16[(size_t)NBH * S_LEN * 32];    // attn Q fp16 (SC folded), swizzled 64B rows
__device__ __half         g_Kp16[(size_t)NBH * S_LEN * 32];    // attn K fp16, swizzled 64B rows
__device__ __half         g_Vp16[(size_t)NBH * 32 * 2048];     // attn V^T fp16, 4KB/tile swizzled
// fp16 GEMM A-format: [blk 0..3][m][64 fp16], 128B rows, 3-bit chunk swizzle
__device__ __half         g_Aq16[(size_t)4 * M_ROWS * 64];
__device__ __half         g_Ak16[(size_t)4 * M_ROWS * 64];
__device__ __half         g_Av16[(size_t)4 * M_ROWS * 64];
__device__ __half         g_Op16[(size_t)4 * M_ROWS * 64];     // attn output, packed directly
__device__ __half         g_Wp16[(size_t)4 * 4 * 256 * 64];    // weights q,k,v,o

#define ATTN_SC (0.17677669529663687f * 1.4426950408889634f)   // 1/sqrt(32)*log2e

// ---------------------------------------------------------------------------
// Helpers
// ---------------------------------------------------------------------------
__device__ __forceinline__ uint32_t smem_u32(const void* p) {
    uint32_t a;
    asm("{ .reg .u64 t; cvta.to.shared.u64 t, %1; cvt.u32.u64 %0, t; }" : "=r"(a) : "l"(p));
    return a;
}
__device__ __forceinline__ float ex2(float x) {
    float y; asm("ex2.approx.f32 %0, %1;" : "=f"(y) : "f"(x)); return y;
}
// pack two fp32 -> f16x2 (lo = p0, hi = p1)
#define CVT_F16X2(result, p0, p1) \
    asm("cvt.rn.f16x2.f32 %0, %1, %2;" : "=r"(result) : "f"(p1), "f"(p0))

__device__ __forceinline__ void ldm_x4(uint32_t (&r)[4], uint32_t addr) {
    asm volatile("ldmatrix.sync.aligned.m8n8.x4.shared.b16 {%0,%1,%2,%3}, [%4];"
                 : "=r"(r[0]), "=r"(r[1]), "=r"(r[2]), "=r"(r[3]) : "r"(addr));
}
__device__ __forceinline__ void mma_f16(float (&d)[4], const uint32_t* a, const uint32_t* b) {
    asm volatile("mma.sync.aligned.m16n8k16.row.col.f32.f16.f16.f32 "
                 "{%0,%1,%2,%3}, {%4,%5,%6,%7}, {%8,%9}, {%0,%1,%2,%3};"
                 : "+f"(d[0]), "+f"(d[1]), "+f"(d[2]), "+f"(d[3])
                 : "r"(a[0]), "r"(a[1]), "r"(a[2]), "r"(a[3]), "r"(b[0]), "r"(b[1]));
}

#define CP16(dst, src) \
    asm volatile("cp.async.cg.shared.global [%0], [%1], 16;" :: "r"(dst), "l"(src))
#define CP_COMMIT() asm volatile("cp.async.commit_group;" ::: "memory")
#define CP_WAIT0()  asm volatile("cp.async.wait_group 0;" ::: "memory")

// ---------------------------------------------------------------------------
// Mask bit-pack v2: one thread = 8 elements (two int4 loads -> one byte).
// ---------------------------------------------------------------------------
__global__ __launch_bounds__(256) void pack_mask_kernel(
    const int4* __restrict__ mask, unsigned char* __restrict__ bits)
{
    int idx = blockIdx.x * 256 + threadIdx.x;
    int4 a = mask[idx * 2];
    int4 b = mask[idx * 2 + 1];
    unsigned byte = (unsigned)(a.x != 0)
                  | ((unsigned)(a.y != 0) << 1)
                  | ((unsigned)(a.z != 0) << 2)
                  | ((unsigned)(a.w != 0) << 3)
                  | ((unsigned)(b.x != 0) << 4)
                  | ((unsigned)(b.y != 0) << 5)
                  | ((unsigned)(b.z != 0) << 6)
                  | ((unsigned)(b.w != 0) << 7);
    bits[idx] = (unsigned char)byte;
}

// ---------------------------------------------------------------------------
// pack_a3 fp16: one thread = 4 dims -> one uint2. Layout [blk][m][64], 128B
// rows, chunk swizzle ch ^ (m&7) (same row pattern as proven V image).
// ---------------------------------------------------------------------------
__global__ __launch_bounds__(256) void pack_a3_kernel(
    const float* __restrict__ q, const float* __restrict__ k, const float* __restrict__ v,
    __half* __restrict__ Aq, __half* __restrict__ Ak, __half* __restrict__ Av)
{
    const float* src; __half* dst;
    if (blockIdx.y == 0)      { src = q; dst = Aq; }
    else if (blockIdx.y == 1) { src = k; dst = Ak; }
    else                      { src = v; dst = Av; }
    int idx = blockIdx.x * 256 + threadIdx.x;     // 8192 m * 64 quads
    int c4g = idx & 63;
    int m   = idx >> 6;
    float4 v4 = *(const float4*)&src[(size_t)m * DMODEL + c4g * 4];
    uint32_t p0, p1;
    CVT_F16X2(p0, v4.x, v4.y);
    CVT_F16X2(p1, v4.z, v4.w);
    const int blk = c4g >> 4;
    const int c   = (c4g * 4) & 63;
    uint32_t* dp = (uint32_t*)(dst + (((size_t)blk * M_ROWS + m) << 6));
    const int word = (((c >> 3) ^ (m & 7)) << 2) + ((c & 7) >> 1);
    *(uint2*)&dp[word] = make_uint2(p0, p1);
}

// ---------------------------------------------------------------------------
// Pack all 4 weight matrices fp16: [w][blk][n][64], swizzled
// ---------------------------------------------------------------------------
__global__ __launch_bounds__(256) void pack_w_kernel(
    const float* __restrict__ Wq, const float* __restrict__ Wk,
    const float* __restrict__ Wv, const float* __restrict__ Wo,
    __half* __restrict__ Wp)
{
    int idx = blockIdx.x * 256 + threadIdx.x;     // 4w * 256n * 64 quads
    int c4g = idx & 63;
    int n   = (idx >> 6) & 255;
    int w   = idx >> 14;
    const float* W = (w == 0) ? Wq : (w == 1) ? Wk : (w == 2) ? Wv : Wo;
    float4 v4 = *(const float4*)&W[(size_t)n * DMODEL + c4g * 4];
    uint32_t p0, p1;
    CVT_F16X2(p0, v4.x, v4.y);
    CVT_F16X2(p1, v4.z, v4.w);
    const int blk = c4g >> 4;
    const int c   = (c4g * 4) & 63;
    uint32_t* dp = (uint32_t*)(Wp + (((size_t)(w * 4 + blk) * 256 + n) << 6));
    const int word = (((c >> 3) ^ (n & 7)) << 2) + ((c & 7) >> 1);
    *(uint2*)&dp[word] = make_uint2(p0, p1);
}

// ---------------------------------------------------------------------------
// V pack (fp16 single image): per (b,h,ktile): V^T 32d x 64key, 128B rows
// ---------------------------------------------------------------------------
__global__ __launch_bounds__(256) void pack_v16_kernel(
    const float* __restrict__ V, __half* __restrict__ Vp)
{
    int idx = blockIdx.x * 256 + threadIdx.x;      // NBH*32*32*64
    int key = idx & 63;
    int d   = (idx >> 6) & 31;
    int t   = (idx >> 11) & 31;
    int bh  = idx >> 16;
    int b = bh >> 3, h = bh & 7;
    float v = V[(size_t)(b * S_LEN + t * 64 + key) * DMODEL + h * HD + d];
    Vp[(size_t)bh * 65536 + t * 2048 + d * 64 + (key ^ ((d & 7) << 3))] = __float2half_rn(v);
}

// ---------------------------------------------------------------------------
// fp16 single-pass tensor-core GEMM: C[M,256] = A @ W^T + bias.
// A [blk][m][64 fp16] 128B rows; W [blk][n][64 fp16]. K-chunks of 64 dims,
// double-buffered (A 16KB + W 8KB per buffer). Single sync per chunk.
// MODE 0: fp32 output. MODE 1: fp16 attn-image output ((val+bias)*oscale).
// ---------------------------------------------------------------------------
#define GEMM_SMEM 49152

template <int MODE>
__device__ __forceinline__ void gemm16_body(
    const __half* __restrict__ Ap, const __half* __restrict__ Wp,
    const float* __restrict__ bias, void* __restrict__ Cout, float oscale, char* smem)
{
    const uint32_t sb = smem_u32(smem);
    const int tid = threadIdx.x, lane = tid & 31, wid = tid >> 5;
    const int n0 = blockIdx.x * 64, m0 = blockIdx.y * 128;
    const char* Ab = (const char*)Ap;
    const char* Wb = (const char*)Wp;

    auto stage = [&](int t, uint32_t buf) {
        #pragma unroll
        for (int i = 0; i < 4; i++) {
            int g = i * 256 + tid;
            int row = g >> 3, ch = g & 7;
            CP16(sb + buf + row * 128 + ch * 16,
                 Ab + ((size_t)t * M_ROWS + m0 + row) * 128 + ch * 16);
        }
        #pragma unroll
        for (int i = 0; i < 2; i++) {
            int g = i * 256 + tid;
            int row = g >> 3, ch = g & 7;
            CP16(sb + buf + 16384 + row * 128 + ch * 16,
                 Wb + ((size_t)t * 256 + n0 + row) * 128 + ch * 16);
        }
        CP_COMMIT();
    };

    stage(0, 0);

    float c[8][4];
    #pragma unroll
    for (int i = 0; i < 8; i++)
        #pragma unroll
        for (int j = 0; j < 4; j++) c[i][j] = 0.f;

    const int m_off = (lane & 7) + ((lane >> 3) & 1) * 8;
    const int coff  = (lane >> 4) & 1;
    const int m = wid * 16 + m_off;
    const int kb_row = (lane & 7) + ((lane >> 4) & 1) * 8;
    const int kb_c   = (lane >> 3) & 1;

    for (int t = 0; t < 4; t++) {
        CP_WAIT0();
        __syncthreads();
        if (t < 3) stage(t + 1, ((t + 1) & 1) * 24576);

        const uint32_t abase = sb + (t & 1) * 24576;
        const uint32_t wbase = abase + 16384;

        #pragma unroll
        for (int k16 = 0; k16 < 4; k16++) {
            const int ch = 2 * k16 + coff;
            uint32_t af[4];
            ldm_x4(af, abase + m * 128 + ((ch ^ (m & 7)) << 4));
            #pragma unroll
            for (int np = 0; np < 4; np++) {
                const int n = np * 16 + kb_row;
                const int wch = 2 * k16 + kb_c;
                uint32_t bf[4];
                ldm_x4(bf, wbase + n * 128 + ((wch ^ (n & 7)) << 4));
                mma_f16(c[2 * np],     af, bf + 0);
                mma_f16(c[2 * np + 1], af, bf + 2);
            }
        }
    }

    const int r0 = m0 + wid * 16 + (lane >> 2);
    if (MODE == 0) {
        float* C = (float*)Cout;
        #pragma unroll
        for (int np = 0; np < 4; np++) {
            #pragma unroll
            for (int half = 0; half < 2; half++) {
                const int col = n0 + np * 16 + half * 8 + (lane & 3) * 2;
                const float b0 = bias[col], b1 = bias[col + 1];
                float* p0 = C + (size_t)r0 * DMODEL + col;
                *(float2*)p0 = make_float2(c[2 * np + half][0] + b0, c[2 * np + half][1] + b1);
                *(float2*)(p0 + 8 * DMODEL) = make_float2(c[2 * np + half][2] + b0, c[2 * np + half][3] + b1);
            }
        }
    } else {
        // fp16 attn image: row (b,h,s) -> 32 halves at ((b*8+h)*2048+s)*32,
        // halves index d ^ (((s>>1)&3)<<3). Note sw(s) == sw(s+8).
        uint32_t* P32 = (uint32_t*)Cout;
        const int bb = r0 >> 11, s = r0 & (S_LEN - 1);
        const int sw = ((s >> 1) & 3) << 3;
        #pragma unroll
        for (int np = 0; np < 4; np++) {
            #pragma unroll
            for (int half = 0; half < 2; half++) {
                const int col = n0 + np * 16 + half * 8 + (lane & 3) * 2;
                const int hh = col >> 5, d = col & 31;
                const float b0 = bias[col], b1 = bias[col + 1];
                const size_t base = ((size_t)(bb * 8 + hh) * S_LEN + s) * 32;
                uint32_t p01, p23;
                CVT_F16X2(p01, (c[2 * np + half][0] + b0) * oscale,
                               (c[2 * np + half][1] + b1) * oscale);
                CVT_F16X2(p23, (c[2 * np + half][2] + b0) * oscale,
                               (c[2 * np + half][3] + b1) * oscale);
                P32[(base + (d ^ sw)) >> 1]       = p01;   // row s
                P32[(base + 256 + (d ^ sw)) >> 1] = p23;   // row s+8
            }
        }
    }
}

__global__ __launch_bounds__(256, 2) void gemm16_qkv(
    const __half* __restrict__ Aq, const __half* __restrict__ Ak,
    const __half* __restrict__ Av, const __half* __restrict__ Wp,
    const float* __restrict__ bq, const float* __restrict__ bk, const float* __restrict__ bv,
    __half* __restrict__ Qp, __half* __restrict__ Kp, float* __restrict__ Vo)
{
    extern __shared__ char smem[];
    if (blockIdx.z == 0)
        gemm16_body<1>(Aq, Wp,                     bq, Qp, ATTN_SC, smem);
    else if (blockIdx.z == 1)
        gemm16_body<1>(Ak, Wp + (size_t)1 * 65536, bk, Kp, 1.0f,    smem);
    else
        gemm16_body<0>(Av, Wp + (size_t)2 * 65536, bv, Vo, 1.0f,    smem);
}

__global__ __launch_bounds__(256, 2) void gemm16_one(
    const __half* __restrict__ Ap, const __half* __restrict__ Wp,
    const float* __restrict__ bias, float* __restrict__ C)
{
    extern __shared__ char smem[];
    gemm16_body<0>(Ap, Wp, bias, C, 1.0f, smem);
}

// ---------------------------------------------------------------------------
// fp16 single-pass mma flash attention (R14-proven body), 128-key iterations.
// Epilogue writes fp16 single A-format into g_Op16.
// smem: KV double buffer [2][16KB] at 0 (K 8KB | V 8KB); Q fp16 8KB at 32KB.
// ---------------------------------------------------------------------------
#define SM_KV 0
#define SM_Q  32768
#define ATTN_SMEM 40960

__global__ __launch_bounds__(256, 2) void attn_mma_kernel(
    const __half* __restrict__ Qp, const __half* __restrict__ Kp,
    const __half* __restrict__ Vp, const unsigned* __restrict__ mbits)
{
    extern __shared__ char smem[];
    const uint32_t sb = smem_u32(smem);
    const int tid = threadIdx.x;
    const int lane = tid & 31, wid = tid >> 5;
    const int b = blockIdx.z, h = blockIdx.y;
    const int q0 = blockIdx.x * 128;
    const int bh = b * NHEADS + h;

    const char* ksrc = (const char*)(Kp + (size_t)bh * 65536);
    const char* vsrc = (const char*)(Vp + (size_t)bh * 65536);
    const char* qsrc = (const char*)(Qp + ((size_t)bh * S_LEN + q0) * 32);

    // ---- prefetch Q tile (8KB) + KV iteration 0 (16KB) ----
    {
        uint32_t dq = sb + SM_Q;
        CP16(dq + tid * 16,         qsrc + tid * 16);
        CP16(dq + (tid + 256) * 16, qsrc + (tid + 256) * 16);
        uint32_t d0 = sb + SM_KV;
        CP16(d0 + tid * 16,                ksrc + tid * 16);
        CP16(d0 + (tid + 256) * 16,        ksrc + (tid + 256) * 16);
        CP16(d0 + 8192 + tid * 16,         vsrc + tid * 16);
        CP16(d0 + 8192 + (tid + 256) * 16, vsrc + (tid + 256) * 16);
        CP_COMMIT();
    }
    CP_WAIT0();
    __syncthreads();

    // ---- Q A-fragments (fp16, single image) ----
    uint32_t qf[2][4];
    {
        const int m_off = (lane & 7) + ((lane >> 3) & 1) * 8;
        const int coff  = (lane >> 4) & 1;
        const int m = wid * 16 + m_off;
        const uint32_t qrow = sb + SM_Q + m * 64;
        const int swq = (m >> 1) & 3;
        #pragma unroll
        for (int k16 = 0; k16 < 2; k16++) {
            int ch = 2 * k16 + coff;
            ldm_x4(qf[k16], qrow + ((ch ^ swq) << 4));
        }
    }

    const int kb_row = (lane & 7) + ((lane >> 4) & 1) * 8;
    const int kb_c   = (lane >> 3) & 1;

    const unsigned* mb0 = mbits + (size_t)(b * S_LEN + q0 + wid * 16 + (lane >> 2)) * MWORDS;
    const unsigned* mb1 = mb0 + 8 * MWORDS;

    float l0 = 0.f, l1 = 0.f;
    float o[4][4];
    #pragma unroll
    for (int i = 0; i < 4; i++)
        #pragma unroll
        for (int j = 0; j < 4; j++) o[i][j] = 0.f;

    for (int it = 0; it < 16; it++) {
        if (it) { CP_WAIT0(); __syncthreads(); }

        // prefetch it+1 into the other slot (safe: slot last read at it-1)
        if (it < 15) {
            uint32_t d1 = sb + SM_KV + ((it + 1) & 1) * 16384;
            const char* ks = ksrc + (size_t)(it + 1) * 8192;
            const char* vs = vsrc + (size_t)(it + 1) * 8192;
            CP16(d1 + tid * 16,                ks + tid * 16);
            CP16(d1 + (tid + 256) * 16,        ks + (tid + 256) * 16);
            CP16(d1 + 8192 + tid * 16,         vs + tid * 16);
            CP16(d1 + 8192 + (tid + 256) * 16, vs + (tid + 256) * 16);
            CP_COMMIT();
        }

        const uint32_t slot = sb + SM_KV + (it & 1) * 16384;

        #pragma unroll
        for (int sub = 0; sub < 2; sub++) {
            const uint32_t kbase = slot + sub * 4096;
            const uint32_t vbase = slot + 8192 + sub * 4096;

            // ---- QK^T (fp16): 8 ldm + 16 mma ----
            float c[8][4];
            #pragma unroll
            for (int i = 0; i < 8; i++)
                #pragma unroll
                for (int j = 0; j < 4; j++) c[i][j] = 0.f;

            #pragma unroll
            for (int k16 = 0; k16 < 2; k16++) {
                #pragma unroll
                for (int np = 0; np < 4; np++) {
                    const int key = np * 16 + kb_row;
                    const int ch  = 2 * k16 + kb_c;
                    uint32_t bf[4];
                    ldm_x4(bf, kbase + key * 64 + ((ch ^ ((key >> 1) & 3)) << 4));
                    mma_f16(c[2 * np],     qf[k16], bf + 0);
                    mma_f16(c[2 * np + 1], qf[k16], bf + 2);
                }
            }

            // ---- softmax -> P fp16 fragments ----
            const uint64_t mw0 = *(const uint64_t*)(mb0 + it * 4 + sub * 2);
            const uint64_t mw1 = *(const uint64_t*)(mb1 + it * 4 + sub * 2);
            uint32_t ap[4][4];
            #pragma unroll
            for (int jj = 0; jj < 4; jj++) {
                #pragma unroll
                for (int half = 0; half < 2; half++) {
                    const int j = 2 * jj + half;
                    const int colb = j * 8 + (lane & 3) * 2;
                    float p0 = ((mw0 >> colb)       & 1) ? ex2(c[j][0]) : 0.f;
                    float p1 = ((mw0 >> (colb + 1)) & 1) ? ex2(c[j][1]) : 0.f;
                    float p2 = ((mw1 >> colb)       & 1) ? ex2(c[j][2]) : 0.f;
                    float p3 = ((mw1 >> (colb + 1)) & 1) ? ex2(c[j][3]) : 0.f;
                    l0 += p0 + p1; l1 += p2 + p3;
                    CVT_F16X2(ap[jj][half * 2],     p0, p1);
                    CVT_F16X2(ap[jj][half * 2 + 1], p2, p3);
                }
            }

            // ---- PV (fp16): 8 ldm + 16 mma ----
            #pragma unroll
            for (int k16 = 0; k16 < 4; k16++) {
                #pragma unroll
                for (int np = 0; np < 2; np++) {
                    const int d  = np * 16 + kb_row;
                    const int ch = 2 * k16 + kb_c;
                    uint32_t bv[4];
                    ldm_x4(bv, vbase + d * 128 + ((ch ^ (d & 7)) << 4));
                    mma_f16(o[2 * np],     ap[k16], bv + 0);
                    mma_f16(o[2 * np + 1], ap[k16], bv + 2);
                }
            }
        }
    }

    // ---- finalize: normalize and write fp16 single GEMM-A format ----
    l0 += __shfl_xor_sync(0xffffffffu, l0, 1);
    l0 += __shfl_xor_sync(0xffffffffu, l0, 2);
    l1 += __shfl_xor_sync(0xffffffffu, l1, 1);
    l1 += __shfl_xor_sync(0xffffffffu, l1, 2);
    const float inv0 = 1.f / l0, inv1 = 1.f / l1;

    const int r0g = q0 + wid * 16 + (lane >> 2);
    const int m0r = b * S_LEN + r0g;           // GEMM row index (row r0g)
    const int sw  = r0g & 7;                   // (r0g+8) has the same &7
    uint32_t* Op32 = (uint32_t*)g_Op16;
    #pragma unroll
    for (int j = 0; j < 4; j++) {
        const int d = j * 8 + (lane & 3) * 2;
        const int col = h * HD + d;            // global output dim 0..255
        const int blk = col >> 6, c = col & 63;
        uint32_t p01, p23;
        CVT_F16X2(p01, o[j][0] * inv0, o[j][1] * inv0);
        CVT_F16X2(p23, o[j][2] * inv1, o[j][3] * inv1);
        const size_t base0 = ((size_t)blk * M_ROWS + m0r) * 32;
        const int word = (((c >> 3) ^ sw) << 2) + ((c & 7) >> 1);
        Op32[base0 + word]          = p01;     // row m0r
        Op32[base0 + 8 * 32 + word] = p23;     // row m0r + 8 (same swizzle)
    }
}

// ---------------------------------------------------------------------------
// Launch
// ---------------------------------------------------------------------------
extern "C" void kernel_launch(void* const* d_in, const int* in_sizes, int n_in,
                              void* d_out, int out_size)
{
    const float* query = (const float*)d_in[0];
    const float* key   = (const float*)d_in[1];
    const float* value = (const float*)d_in[2];
    const int*   mask  = (const int*)  d_in[3];
    const float* Wq = (const float*)d_in[4];
    const float* bq = (const float*)d_in[5];
    const float* Wk = (const float*)d_in[6];
    const float* bk = (const float*)d_in[7];
    const float* Wv = (const float*)d_in[8];
    const float* bv = (const float*)d_in[9];
    const float* Wo = (const float*)d_in[10];
    const float* bo = (const float*)d_in[11];
    float* out = (float*)d_out;

    float* Vb;
    unsigned* MBp;
    __half *Qpp, *Kpp, *Vpp, *Aq, *Ak, *Av, *Op, *Wp;
    cudaGetSymbolAddress((void**)&Vb, g_V);
    cudaGetSymbolAddress((void**)&MBp, g_MB);
    cudaGetSymbolAddress((void**)&Qpp, g_Qp16);
    cudaGetSymbolAddress((void**)&Kpp, g_Kp16);
    cudaGetSymbolAddress((void**)&Vpp, g_Vp16);
    cudaGetSymbolAddress((void**)&Aq, g_Aq16);
    cudaGetSymbolAddress((void**)&Ak, g_Ak16);
    cudaGetSymbolAddress((void**)&Av, g_Av16);
    cudaGetSymbolAddress((void**)&Op, g_Op16);
    cudaGetSymbolAddress((void**)&Wp, g_Wp16);

    cudaFuncSetAttribute(attn_mma_kernel, cudaFuncAttributeMaxDynamicSharedMemorySize, ATTN_SMEM);
    cudaFuncSetAttribute(gemm16_qkv, cudaFuncAttributeMaxDynamicSharedMemorySize, GEMM_SMEM);
    cudaFuncSetAttribute(gemm16_one, cudaFuncAttributeMaxDynamicSharedMemorySize, GEMM_SMEM);

    pack_mask_kernel<<<(BATCH * S_LEN * S_LEN) / 8 / 256, 256>>>(
        (const int4*)mask, (unsigned char*)MBp);
    pack_w_kernel<<<(4 * 256 * 64) / 256, 256>>>(Wq, Wk, Wv, Wo, Wp);
    pack_a3_kernel<<<dim3((M_ROWS * 64) / 256, 3), 256>>>(query, key, value, Aq, Ak, Av);

    gemm16_qkv<<<dim3(4, 64, 3), 256, GEMM_SMEM>>>(Aq, Ak, Av, Wp,
                                                   bq, bk, bv, Qpp, Kpp, Vb);

    pack_v16_kernel<<<(NBH * 32 * 32 * 64) / 256, 256>>>(Vb, Vpp);

    dim3 attn_grid(S_LEN / 128, NHEADS, BATCH);   // (16, 8, 4)
    attn_mma_kernel<<<attn_grid, 256, ATTN_SMEM>>>(Qpp, Kpp, Vpp, MBp);

    gemm16_one<<<dim3(4, 64), 256, GEMM_SMEM>>>(Op, Wp + (size_t)3 * 65536, bo, out);
}